// round 13
// baseline (speedup 1.0000x reference)
#include <cuda_runtime.h>

#define DIM      128
#define GRID1    128          // K1: <=148 SMs, all co-resident
#define BLOCK1   512
#define NWARPS   16           // 128 * 16 warps * 4 rows = 8192 rows
#define GRID2    256          // K2: no barrier, any shape
#define BLOCK2   256          // 256 * 8 warps * 4 rows = 8192 rows

// Allocation-free scratch (zero-initialized at load)
__device__ float        g_wbuf[2][DIM]; // parity-alternating w accumulators
__device__ unsigned int g_count = 0;
__device__ unsigned int g_gen   = 0;    // +1 per K1 (monotone across replays)

// ============================================================================
// K1: w = Wq^T Wk X^T X Wv^T hw, accumulated via RED across 128 blocks.
// Identical to the proven R6/R12 pre-barrier pipeline; blocks EXIT after RED.
// ============================================================================
__global__ void __launch_bounds__(BLOCK1, 1)
k1_weights(const float* __restrict__ X,
           const float* __restrict__ Wq,
           const float* __restrict__ Wk,
           const float* __restrict__ Wv,
           const float* __restrict__ head_w) {
    __shared__ float svw[DIM];
    __shared__ float sacc[NWARPS][DIM];
    __shared__ float sred[4][DIM];
    __shared__ float sg[DIM];
    __shared__ float su[DIM];
    __shared__ unsigned s_gen;

    const int tid  = threadIdx.x;
    const int lane = tid & 31;
    const int wrp  = tid >> 5;
    const int bid  = blockIdx.x;
    const int coff = lane * 4;
    const int dq   = tid & 127;
    const int qq   = tid >> 7;

    // X prefetch (in flight during phase 0)
    const int row0 = (bid * NWARPS + wrp) * 4;
    const float4 x0 = *reinterpret_cast<const float4*>(&X[(row0 + 0) * DIM + coff]);
    const float4 x1 = *reinterpret_cast<const float4*>(&X[(row0 + 1) * DIM + coff]);
    const float4 x2 = *reinterpret_cast<const float4*>(&X[(row0 + 2) * DIM + coff]);
    const float4 x3 = *reinterpret_cast<const float4*>(&X[(row0 + 3) * DIM + coff]);

    if (tid == 0)
        s_gen = *(volatile unsigned*)&g_gen;

    // Phase 0: v1 = Wv^T @ head_w
    {
        const int e0 = wrp * 8;
        float ax = 0.f, ay = 0.f, az = 0.f, aw = 0.f;
#pragma unroll
        for (int j = 0; j < 8; ++j) {
            const float  hw = head_w[e0 + j];
            const float4 wv = *reinterpret_cast<const float4*>(&Wv[(e0 + j) * DIM + coff]);
            ax += hw * wv.x; ay += hw * wv.y; az += hw * wv.z; aw += hw * wv.w;
        }
        sacc[wrp][coff + 0] = ax; sacc[wrp][coff + 1] = ay;
        sacc[wrp][coff + 2] = az; sacc[wrp][coff + 3] = aw;
    }
    __syncthreads();
    const unsigned my_gen = s_gen;
    const int      par    = (int)(my_gen & 1u);

    sred[qq][dq] = sacc[qq * 4 + 0][dq] + sacc[qq * 4 + 1][dq]
                 + sacc[qq * 4 + 2][dq] + sacc[qq * 4 + 3][dq];
    __syncthreads();
    if (tid < DIM)
        svw[tid] = sred[0][tid] + sred[1][tid] + sred[2][tid] + sred[3][tid];
    __syncthreads();

    const float v0 = svw[coff + 0];
    const float v1 = svw[coff + 1];
    const float v2 = svw[coff + 2];
    const float v3 = svw[coff + 3];

    // Phase 1: g_p = X^T (X v1)
    float p0 = x0.x * v0 + x0.y * v1 + x0.z * v2 + x0.w * v3;
    float p1 = x1.x * v0 + x1.y * v1 + x1.z * v2 + x1.w * v3;
    float p2 = x2.x * v0 + x2.y * v1 + x2.z * v2 + x2.w * v3;
    float p3 = x3.x * v0 + x3.y * v1 + x3.z * v2 + x3.w * v3;
#pragma unroll
    for (int o = 16; o > 0; o >>= 1) {
        p0 += __shfl_xor_sync(0xffffffffu, p0, o);
        p1 += __shfl_xor_sync(0xffffffffu, p1, o);
        p2 += __shfl_xor_sync(0xffffffffu, p2, o);
        p3 += __shfl_xor_sync(0xffffffffu, p3, o);
    }
    __syncthreads();
    sacc[wrp][coff + 0] = p0 * x0.x + p1 * x1.x + p2 * x2.x + p3 * x3.x;
    sacc[wrp][coff + 1] = p0 * x0.y + p1 * x1.y + p2 * x2.y + p3 * x3.y;
    sacc[wrp][coff + 2] = p0 * x0.z + p1 * x1.z + p2 * x2.z + p3 * x3.z;
    sacc[wrp][coff + 3] = p0 * x0.w + p1 * x1.w + p2 * x2.w + p3 * x3.w;
    __syncthreads();
    sred[qq][dq] = sacc[qq * 4 + 0][dq] + sacc[qq * 4 + 1][dq]
                 + sacc[qq * 4 + 2][dq] + sacc[qq * 4 + 3][dq];
    __syncthreads();
    if (tid < DIM)
        sg[tid] = sred[0][tid] + sred[1][tid] + sred[2][tid] + sred[3][tid];
    __syncthreads();

    // Phase 2b: u_p = Wk @ g_p
    {
        const float s0 = sg[coff + 0], s1 = sg[coff + 1];
        const float s2 = sg[coff + 2], s3 = sg[coff + 3];
        const int r0 = wrp * 8;
        float pu[8];
#pragma unroll
        for (int j = 0; j < 8; ++j) {
            const float4 kk = *reinterpret_cast<const float4*>(&Wk[(r0 + j) * DIM + coff]);
            pu[j] = kk.x * s0 + kk.y * s1 + kk.z * s2 + kk.w * s3;
        }
#pragma unroll
        for (int o = 16; o > 0; o >>= 1) {
#pragma unroll
            for (int j = 0; j < 8; ++j)
                pu[j] += __shfl_xor_sync(0xffffffffu, pu[j], o);
        }
        if (lane == 0) {
#pragma unroll
            for (int j = 0; j < 8; ++j)
                su[r0 + j] = pu[j];
        }
    }
    __syncthreads();

    // Phase 2c: w_p = Wq^T @ u_p -> RED into g_wbuf[par]
    {
        const int e0 = wrp * 8;
        float ax = 0.f, ay = 0.f, az = 0.f, aw = 0.f;
#pragma unroll
        for (int j = 0; j < 8; ++j) {
            const float  uu = su[e0 + j];
            const float4 wq = *reinterpret_cast<const float4*>(&Wq[(e0 + j) * DIM + coff]);
            ax += uu * wq.x; ay += uu * wq.y; az += uu * wq.z; aw += uu * wq.w;
        }
        sacc[wrp][coff + 0] = ax; sacc[wrp][coff + 1] = ay;
        sacc[wrp][coff + 2] = az; sacc[wrp][coff + 3] = aw;
    }
    __syncthreads();
    sred[qq][dq] = sacc[qq * 4 + 0][dq] + sacc[qq * 4 + 1][dq]
                 + sacc[qq * 4 + 2][dq] + sacc[qq * 4 + 3][dq];
    __syncthreads();
    if (tid < DIM) {
        const float wp = sred[0][tid] + sred[1][tid] + sred[2][tid] + sred[3][tid];
        atomicAdd(&g_wbuf[par][tid], wp);
    }
    __syncthreads();

    // Last block bumps the generation (bookkeeping only; ordering to K2 is
    // provided by the stream/graph dependency). Then EXIT — no wait.
    if (tid == 0) {
        __threadfence();
        if (atomicAdd(&g_count, 1u) == GRID1 - 1) {
            g_count = 0;
            __threadfence();
            atomicAdd(&g_gen, 1u);
        }
    }
}

// ============================================================================
// K2: out = X @ w + b. Runs after K1 (graph edge). X is L2-hot. No barrier.
// Also zeroes the next replay's accumulator.
// ============================================================================
__global__ void __launch_bounds__(BLOCK2, 2)
k2_output(const float* __restrict__ X,
          const float* __restrict__ head_b,
          float* __restrict__ out) {
    __shared__ float sw[DIM];

    const int tid  = threadIdx.x;
    const int lane = tid & 31;
    const int wrp  = tid >> 5;
    const int bid  = blockIdx.x;
    const int coff = lane * 4;

    // g_gen is stable here (K1 complete). Used buffer = (gen-1)&1.
    const unsigned gen = *(volatile unsigned*)&g_gen;
    const int used = (int)((gen - 1u) & 1u);

    // Block 0 zeroes the other buffer for the next replay's K1.
    if (bid == 0 && tid < DIM)
        g_wbuf[1 - used][tid] = 0.0f;

    if (tid < DIM)
        sw[tid] = g_wbuf[used][tid];
    __syncthreads();

    const float w0 = sw[coff + 0];
    const float w1 = sw[coff + 1];
    const float w2 = sw[coff + 2];
    const float w3 = sw[coff + 3];
    const float b  = head_b[0];

    const int row0 = (bid * (BLOCK2 / 32) + wrp) * 4;   // 256*8*4 = 8192
    const float4 x0 = *reinterpret_cast<const float4*>(&X[(row0 + 0) * DIM + coff]);
    const float4 x1 = *reinterpret_cast<const float4*>(&X[(row0 + 1) * DIM + coff]);
    const float4 x2 = *reinterpret_cast<const float4*>(&X[(row0 + 2) * DIM + coff]);
    const float4 x3 = *reinterpret_cast<const float4*>(&X[(row0 + 3) * DIM + coff]);

    float q0 = x0.x * w0 + x0.y * w1 + x0.z * w2 + x0.w * w3;
    float q1 = x1.x * w0 + x1.y * w1 + x1.z * w2 + x1.w * w3;
    float q2 = x2.x * w0 + x2.y * w1 + x2.z * w2 + x2.w * w3;
    float q3 = x3.x * w0 + x3.y * w1 + x3.z * w2 + x3.w * w3;
#pragma unroll
    for (int o = 16; o > 0; o >>= 1) {
        q0 += __shfl_xor_sync(0xffffffffu, q0, o);
        q1 += __shfl_xor_sync(0xffffffffu, q1, o);
        q2 += __shfl_xor_sync(0xffffffffu, q2, o);
        q3 += __shfl_xor_sync(0xffffffffu, q3, o);
    }
    if (lane == 0) {
        *reinterpret_cast<float4*>(&out[row0]) =
            make_float4(q0 + b, q1 + b, q2 + b, q3 + b);
    }
}

extern "C" void kernel_launch(void* const* d_in, const int* in_sizes, int n_in,
                              void* d_out, int out_size) {
    const float* X      = (const float*)d_in[0];
    const float* Wq     = (const float*)d_in[1];
    const float* Wk     = (const float*)d_in[2];
    const float* Wv     = (const float*)d_in[3];
    const float* head_w = (const float*)d_in[4];
    const float* head_b = (const float*)d_in[5];
    float* out          = (float*)d_out;

    k1_weights<<<GRID1, BLOCK1>>>(X, Wq, Wk, Wv, head_w);
    k2_output <<<GRID2, BLOCK2>>>(X, head_b, out);
}

// round 14
// speedup vs baseline: 1.1695x; 1.1695x over previous
#include <cuda_runtime.h>

#define DIM      128
#define GRID     128          // <= 148 SMs -> all CTAs co-resident, barrier is safe
#define BLOCK    512
#define NWARPS   16           // 128 blocks * 16 warps * 4 rows = 8192 rows

// Allocation-free scratch + barrier state (zero-initialized at load)
__device__ float        g_wbuf[2][DIM]; // parity-alternating w accumulators
__device__ unsigned int g_count = 0;
__device__ unsigned int g_gen   = 0;    // +1 per launch (monotone across replays)

// Single-stage 16-warp gather: thread t sums sacc[0..15][t] (conflict-free LDS)
__device__ __forceinline__ float gather16(const float (*sacc)[DIM], int t) {
    float s = 0.0f;
#pragma unroll
    for (int w = 0; w < NWARPS; ++w)
        s += sacc[w][t];
    return s;
}

__global__ void __launch_bounds__(BLOCK, 1)
fused_linattn(const float* __restrict__ X,
              const float* __restrict__ Wq,
              const float* __restrict__ Wk,
              const float* __restrict__ Wv,
              const float* __restrict__ head_w,
              const float* __restrict__ head_b,
              float* __restrict__ out) {
    __shared__ float svw[DIM];            // v1
    __shared__ float sacc[NWARPS][DIM];
    __shared__ float sg[DIM];             // this block's g partial
    __shared__ float su[DIM];             // this block's u partial
    __shared__ unsigned s_gen;

    const int tid  = threadIdx.x;
    const int lane = tid & 31;
    const int wrp  = tid >> 5;
    const int bid  = blockIdx.x;
    const int coff = lane * 4;

    // ---- Prefetch X into registers FIRST (in flight during phase 0) --------
    const int row0 = (bid * NWARPS + wrp) * 4;
    const float4 x0 = *reinterpret_cast<const float4*>(&X[(row0 + 0) * DIM + coff]);
    const float4 x1 = *reinterpret_cast<const float4*>(&X[(row0 + 1) * DIM + coff]);
    const float4 x2 = *reinterpret_cast<const float4*>(&X[(row0 + 2) * DIM + coff]);
    const float4 x3 = *reinterpret_cast<const float4*>(&X[(row0 + 3) * DIM + coff]);

    // ---- Bias load off the tail --------------------------------------------
    const float bias = head_b[0];

    if (tid == 0)
        s_gen = *(volatile unsigned*)&g_gen;     // launch generation (uniform)

    // ============ Phase 0: v1 = Wv^T @ head_w, warp-parallel depth-8 ========
    {
        const int e0 = wrp * 8;
        float ax = 0.f, ay = 0.f, az = 0.f, aw = 0.f;
#pragma unroll
        for (int j = 0; j < 8; ++j) {
            const float  hw = head_w[e0 + j];
            const float4 wv = *reinterpret_cast<const float4*>(&Wv[(e0 + j) * DIM + coff]);
            ax += hw * wv.x; ay += hw * wv.y; az += hw * wv.z; aw += hw * wv.w;
        }
        sacc[wrp][coff + 0] = ax; sacc[wrp][coff + 1] = ay;
        sacc[wrp][coff + 2] = az; sacc[wrp][coff + 3] = aw;
    }
    __syncthreads();

    const unsigned my_gen = s_gen;
    const int      par    = (int)(my_gen & 1u);

    if (tid < DIM)
        svw[tid] = gather16(sacc, tid);
    __syncthreads();

    const float v0 = svw[coff + 0];
    const float v1 = svw[coff + 1];
    const float v2 = svw[coff + 2];
    const float v3 = svw[coff + 3];

    // ============ Phase 1: block-local g = X^T (X v1), X in regs ============
    float p0 = x0.x * v0 + x0.y * v1 + x0.z * v2 + x0.w * v3;
    float p1 = x1.x * v0 + x1.y * v1 + x1.z * v2 + x1.w * v3;
    float p2 = x2.x * v0 + x2.y * v1 + x2.z * v2 + x2.w * v3;
    float p3 = x3.x * v0 + x3.y * v1 + x3.z * v2 + x3.w * v3;
#pragma unroll
    for (int o = 16; o > 0; o >>= 1) {
        p0 += __shfl_xor_sync(0xffffffffu, p0, o);
        p1 += __shfl_xor_sync(0xffffffffu, p1, o);
        p2 += __shfl_xor_sync(0xffffffffu, p2, o);
        p3 += __shfl_xor_sync(0xffffffffu, p3, o);
    }
    __syncthreads();   // sacc reuse guard
    sacc[wrp][coff + 0] = p0 * x0.x + p1 * x1.x + p2 * x2.x + p3 * x3.x;
    sacc[wrp][coff + 1] = p0 * x0.y + p1 * x1.y + p2 * x2.y + p3 * x3.y;
    sacc[wrp][coff + 2] = p0 * x0.z + p1 * x1.z + p2 * x2.z + p3 * x3.z;
    sacc[wrp][coff + 3] = p0 * x0.w + p1 * x1.w + p2 * x2.w + p3 * x3.w;
    __syncthreads();
    if (tid < DIM)
        sg[tid] = gather16(sacc, tid);
    __syncthreads();

    // ============ Phase 2 (pre-barrier, per block): w_p = Wq^T Wk g_p =======
    // 2b: u_p = Wk @ g_p (8 rows per warp, shfl reduce)
    {
        const float s0 = sg[coff + 0], s1 = sg[coff + 1];
        const float s2 = sg[coff + 2], s3 = sg[coff + 3];
        const int r0 = wrp * 8;
        float pu[8];
#pragma unroll
        for (int j = 0; j < 8; ++j) {
            const float4 kk = *reinterpret_cast<const float4*>(&Wk[(r0 + j) * DIM + coff]);
            pu[j] = kk.x * s0 + kk.y * s1 + kk.z * s2 + kk.w * s3;
        }
#pragma unroll
        for (int o = 16; o > 0; o >>= 1) {
#pragma unroll
            for (int j = 0; j < 8; ++j)
                pu[j] += __shfl_xor_sync(0xffffffffu, pu[j], o);
        }
        if (lane == 0) {
#pragma unroll
            for (int j = 0; j < 8; ++j)
                su[r0 + j] = pu[j];
        }
    }
    __syncthreads();

    // 2c: w_p = Wq^T @ u_p (depth-8 per warp) -> single-stage reduce -> RED
    {
        const int e0 = wrp * 8;
        float ax = 0.f, ay = 0.f, az = 0.f, aw = 0.f;
#pragma unroll
        for (int j = 0; j < 8; ++j) {
            const float  uu = su[e0 + j];
            const float4 wq = *reinterpret_cast<const float4*>(&Wq[(e0 + j) * DIM + coff]);
            ax += uu * wq.x; ay += uu * wq.y; az += uu * wq.z; aw += uu * wq.w;
        }
        sacc[wrp][coff + 0] = ax; sacc[wrp][coff + 1] = ay;
        sacc[wrp][coff + 2] = az; sacc[wrp][coff + 3] = aw;
    }
    __syncthreads();
    if (tid < DIM)
        atomicAdd(&g_wbuf[par][tid], gather16(sacc, tid));   // RED (no return)
    __syncthreads();

    // ============ Barrier: count arrivals; last block releases ==============
    if (tid == 0) {
        __threadfence();                        // publish this block's REDs
        if (atomicAdd(&g_count, 1u) == GRID - 1) {
            g_count = 0;
            __threadfence();
            atomicAdd(&g_gen, 1u);              // release: w is complete
        } else {
            while (*(volatile unsigned*)&g_gen == my_gen)
                __nanosleep(64);
        }
        __threadfence();                        // acquire
    }
    __syncthreads();

    // ---- Block 0 zeroes NEXT launch's accumulator (post-barrier shadow) ----
    if (bid == 0 && tid < DIM)
        g_wbuf[1 - par][tid] = 0.0f;

    // ============ Phase 3: out = X @ w + b (X still in registers) ===========
    const float4 wv4 = *reinterpret_cast<const float4*>(&g_wbuf[par][coff]);
    const float w0 = wv4.x, w1 = wv4.y, w2 = wv4.z, w3 = wv4.w;

    float q0 = x0.x * w0 + x0.y * w1 + x0.z * w2 + x0.w * w3;
    float q1 = x1.x * w0 + x1.y * w1 + x1.z * w2 + x1.w * w3;
    float q2 = x2.x * w0 + x2.y * w1 + x2.z * w2 + x2.w * w3;
    float q3 = x3.x * w0 + x3.y * w1 + x3.z * w2 + x3.w * w3;
#pragma unroll
    for (int o = 16; o > 0; o >>= 1) {
        q0 += __shfl_xor_sync(0xffffffffu, q0, o);
        q1 += __shfl_xor_sync(0xffffffffu, q1, o);
        q2 += __shfl_xor_sync(0xffffffffu, q2, o);
        q3 += __shfl_xor_sync(0xffffffffu, q3, o);
    }
    if (lane == 0) {
        *reinterpret_cast<float4*>(&out[row0]) =
            make_float4(q0 + bias, q1 + bias, q2 + bias, q3 + bias);
    }
}

extern "C" void kernel_launch(void* const* d_in, const int* in_sizes, int n_in,
                              void* d_out, int out_size) {
    const float* X      = (const float*)d_in[0];
    const float* Wq     = (const float*)d_in[1];
    const float* Wk     = (const float*)d_in[2];
    const float* Wv     = (const float*)d_in[3];
    const float* head_w = (const float*)d_in[4];
    const float* head_b = (const float*)d_in[5];
    float* out          = (float*)d_out;

    fused_linattn<<<GRID, BLOCK>>>(X, Wq, Wk, Wv, head_w, head_b, out);
}

// round 15
// speedup vs baseline: 1.2186x; 1.0419x over previous
#include <cuda_runtime.h>

#define DIM      128
#define GRID     128          // <= 148 SMs -> all CTAs co-resident, barrier is safe
#define BLOCK    512
#define NWARPS   16           // 128 blocks * 16 warps * 4 rows = 8192 rows

// Allocation-free scratch + barrier state (zero-initialized at load)
__device__ float        g_wbuf[2][DIM]; // parity-alternating w accumulators
__device__ unsigned int g_count = 0;
__device__ unsigned int g_gen   = 0;    // +1 per launch (monotone across replays)

// Single-stage 16-warp gather: thread t sums sacc[0..15][t] (conflict-free LDS)
__device__ __forceinline__ float gather16(const float (*sacc)[DIM], int t) {
    float s = 0.0f;
#pragma unroll
    for (int w = 0; w < NWARPS; ++w)
        s += sacc[w][t];
    return s;
}

__global__ void __launch_bounds__(BLOCK, 1)
fused_linattn(const float* __restrict__ X,
              const float* __restrict__ Wq,
              const float* __restrict__ Wk,
              const float* __restrict__ Wv,
              const float* __restrict__ head_w,
              const float* __restrict__ head_b,
              float* __restrict__ out) {
    __shared__ float svw[DIM];            // v1
    __shared__ float sacc[NWARPS][DIM];
    __shared__ float sg[DIM];             // this block's g partial
    __shared__ unsigned s_gen;

    const int tid  = threadIdx.x;
    const int lane = tid & 31;
    const int wrp  = tid >> 5;
    const int bid  = blockIdx.x;
    const int coff = lane * 4;

    // ---- Prefetch X into registers FIRST (in flight during phase 0) --------
    const int row0 = (bid * NWARPS + wrp) * 4;
    const float4 x0 = *reinterpret_cast<const float4*>(&X[(row0 + 0) * DIM + coff]);
    const float4 x1 = *reinterpret_cast<const float4*>(&X[(row0 + 1) * DIM + coff]);
    const float4 x2 = *reinterpret_cast<const float4*>(&X[(row0 + 2) * DIM + coff]);
    const float4 x3 = *reinterpret_cast<const float4*>(&X[(row0 + 3) * DIM + coff]);

    // ---- Bias load off the tail --------------------------------------------
    const float bias = head_b[0];

    if (tid == 0)
        s_gen = *(volatile unsigned*)&g_gen;     // launch generation (uniform)

    // ============ Phase 0: v1 = Wv^T @ head_w, warp-parallel depth-8 ========
    {
        const int e0 = wrp * 8;
        float ax = 0.f, ay = 0.f, az = 0.f, aw = 0.f;
#pragma unroll
        for (int j = 0; j < 8; ++j) {
            const float  hw = head_w[e0 + j];
            const float4 wv = *reinterpret_cast<const float4*>(&Wv[(e0 + j) * DIM + coff]);
            ax += hw * wv.x; ay += hw * wv.y; az += hw * wv.z; aw += hw * wv.w;
        }
        sacc[wrp][coff + 0] = ax; sacc[wrp][coff + 1] = ay;
        sacc[wrp][coff + 2] = az; sacc[wrp][coff + 3] = aw;
    }
    __syncthreads();

    const unsigned my_gen = s_gen;
    const int      par    = (int)(my_gen & 1u);

    if (tid < DIM)
        svw[tid] = gather16(sacc, tid);
    __syncthreads();

    const float v0 = svw[coff + 0];
    const float v1 = svw[coff + 1];
    const float v2 = svw[coff + 2];
    const float v3 = svw[coff + 3];

    // ============ Phase 1: block-local g = X^T (X v1), X in regs ============
    float p0 = x0.x * v0 + x0.y * v1 + x0.z * v2 + x0.w * v3;
    float p1 = x1.x * v0 + x1.y * v1 + x1.z * v2 + x1.w * v3;
    float p2 = x2.x * v0 + x2.y * v1 + x2.z * v2 + x2.w * v3;
    float p3 = x3.x * v0 + x3.y * v1 + x3.z * v2 + x3.w * v3;
#pragma unroll
    for (int o = 16; o > 0; o >>= 1) {
        p0 += __shfl_xor_sync(0xffffffffu, p0, o);
        p1 += __shfl_xor_sync(0xffffffffu, p1, o);
        p2 += __shfl_xor_sync(0xffffffffu, p2, o);
        p3 += __shfl_xor_sync(0xffffffffu, p3, o);
    }
    __syncthreads();   // sacc reuse guard
    sacc[wrp][coff + 0] = p0 * x0.x + p1 * x1.x + p2 * x2.x + p3 * x3.x;
    sacc[wrp][coff + 1] = p0 * x0.y + p1 * x1.y + p2 * x2.y + p3 * x3.y;
    sacc[wrp][coff + 2] = p0 * x0.z + p1 * x1.z + p2 * x2.z + p3 * x3.z;
    sacc[wrp][coff + 3] = p0 * x0.w + p1 * x1.w + p2 * x2.w + p3 * x3.w;
    __syncthreads();
    if (tid < DIM)
        sg[tid] = gather16(sacc, tid);
    __syncthreads();

    // ============ Phase 2 (pre-barrier, per block): w_p = Wq^T Wk g_p =======
    // FUSED 2b+2c: warp w computes u rows [8w,8w+8) via butterfly; after the
    // butterfly every lane holds pu[j], which is exactly the u[e] range this
    // warp needs for its Wq^T slice -> no smem round trip, no extra barrier.
    {
        const float s0 = sg[coff + 0], s1 = sg[coff + 1];
        const float s2 = sg[coff + 2], s3 = sg[coff + 3];
        const int r0 = wrp * 8;
        float pu[8];
#pragma unroll
        for (int j = 0; j < 8; ++j) {
            const float4 kk = *reinterpret_cast<const float4*>(&Wk[(r0 + j) * DIM + coff]);
            pu[j] = kk.x * s0 + kk.y * s1 + kk.z * s2 + kk.w * s3;
        }
#pragma unroll
        for (int o = 16; o > 0; o >>= 1) {
#pragma unroll
            for (int j = 0; j < 8; ++j)
                pu[j] += __shfl_xor_sync(0xffffffffu, pu[j], o);
        }
        // 2c directly from registers: w_p[col] += sum_j pu[j] * Wq[r0+j][col]
        float ax = 0.f, ay = 0.f, az = 0.f, aw = 0.f;
#pragma unroll
        for (int j = 0; j < 8; ++j) {
            const float4 wq = *reinterpret_cast<const float4*>(&Wq[(r0 + j) * DIM + coff]);
            ax += pu[j] * wq.x; ay += pu[j] * wq.y;
            az += pu[j] * wq.z; aw += pu[j] * wq.w;
        }
        sacc[wrp][coff + 0] = ax; sacc[wrp][coff + 1] = ay;
        sacc[wrp][coff + 2] = az; sacc[wrp][coff + 3] = aw;
    }
    __syncthreads();
    if (tid < DIM)
        atomicAdd(&g_wbuf[par][tid], gather16(sacc, tid));   // RED (no return)
    __syncthreads();

    // ============ Barrier: count arrivals; last block releases ==============
    if (tid == 0) {
        __threadfence();                        // publish this block's REDs
        if (atomicAdd(&g_count, 1u) == GRID - 1) {
            g_count = 0;
            __threadfence();
            atomicAdd(&g_gen, 1u);              // release: w is complete
        } else {
            while (*(volatile unsigned*)&g_gen == my_gen)
                __nanosleep(64);
        }
        __threadfence();                        // acquire
    }
    __syncthreads();

    // ---- Block 0 zeroes NEXT launch's accumulator (post-barrier shadow) ----
    if (bid == 0 && tid < DIM)
        g_wbuf[1 - par][tid] = 0.0f;

    // ============ Phase 3: out = X @ w + b (X still in registers) ===========
    const float4 wv4 = *reinterpret_cast<const float4*>(&g_wbuf[par][coff]);
    const float w0 = wv4.x, w1 = wv4.y, w2 = wv4.z, w3 = wv4.w;

    float q0 = x0.x * w0 + x0.y * w1 + x0.z * w2 + x0.w * w3;
    float q1 = x1.x * w0 + x1.y * w1 + x1.z * w2 + x1.w * w3;
    float q2 = x2.x * w0 + x2.y * w1 + x2.z * w2 + x2.w * w3;
    float q3 = x3.x * w0 + x3.y * w1 + x3.z * w2 + x3.w * w3;
#pragma unroll
    for (int o = 16; o > 0; o >>= 1) {
        q0 += __shfl_xor_sync(0xffffffffu, q0, o);
        q1 += __shfl_xor_sync(0xffffffffu, q1, o);
        q2 += __shfl_xor_sync(0xffffffffu, q2, o);
        q3 += __shfl_xor_sync(0xffffffffu, q3, o);
    }
    if (lane == 0) {
        *reinterpret_cast<float4*>(&out[row0]) =
            make_float4(q0 + bias, q1 + bias, q2 + bias, q3 + bias);
    }
}

extern "C" void kernel_launch(void* const* d_in, const int* in_sizes, int n_in,
                              void* d_out, int out_size) {
    const float* X      = (const float*)d_in[0];
    const float* Wq     = (const float*)d_in[1];
    const float* Wk     = (const float*)d_in[2];
    const float* Wv     = (const float*)d_in[3];
    const float* head_w = (const float*)d_in[4];
    const float* head_b = (const float*)d_in[5];
    float* out          = (float*)d_out;

    fused_linattn<<<GRID, BLOCK>>>(X, Wq, Wk, Wv, head_w, head_b, out);
}